// round 1
// baseline (speedup 1.0000x reference)
#include <cuda_runtime.h>
#include <cstdint>

#define MAXN 1000000
#define M 9

// Scratch (allocation-free rule: __device__ globals)
__device__ float4 d_pk[MAXN];   // {x, y, ut, ut1}
__device__ float4 d_g[MAXN];    // {gx, gy, g1x, g1y}  (grad1 for ut and ut1)
__device__ double d_acc[2];     // [0] = loss_u, [1] = loss_f

__global__ void k_init() {
    d_acc[0] = 0.0;
    d_acc[1] = 0.0;
}

// Block-level reduce a float, one double atomicAdd per block.
__device__ __forceinline__ void block_reduce_add(float v, double* target) {
    __shared__ float warp_sums[32];
    int lane = threadIdx.x & 31;
    int wid  = threadIdx.x >> 5;
    #pragma unroll
    for (int off = 16; off > 0; off >>= 1)
        v += __shfl_down_sync(0xFFFFFFFFu, v, off);
    if (lane == 0) warp_sums[wid] = v;
    __syncthreads();
    int nwarps = (blockDim.x + 31) >> 5;
    if (wid == 0) {
        float s = (lane < nwarps) ? warp_sums[lane] : 0.0f;
        #pragma unroll
        for (int off = 16; off > 0; off >>= 1)
            s += __shfl_down_sync(0xFFFFFFFFu, s, off);
        if (lane == 0) atomicAdd(target, (double)s);
    }
}

// K1: build pack array + loss_u
__global__ void k_pack(const float* __restrict__ up,
                       const float* __restrict__ usol,
                       const float* __restrict__ ut,
                       const float* __restrict__ x,
                       const float* __restrict__ ut1,
                       int n) {
    int i = blockIdx.x * blockDim.x + threadIdx.x;
    float lu = 0.0f;
    if (i < n) {
        float4 pk;
        pk.x = x[2 * i];
        pk.y = x[2 * i + 1];
        pk.z = ut[i];
        pk.w = ut1[i];
        d_pk[i] = pk;
        float d = up[i] - usol[i];
        lu = d * d;
    }
    block_reduce_add(lu, &d_acc[0]);
}

// K2: grad1 for ut and ut1 simultaneously (shared x gathers via pack)
__global__ void k_grad1(const int* __restrict__ idx,
                        const float4* __restrict__ inv,
                        int n) {
    int k = blockIdx.x * blockDim.x + threadIdx.x;
    if (k >= n) return;
    float4 pk = d_pk[k];
    float sx = 0.f, sy = 0.f, s1x = 0.f, s1y = 0.f;
    #pragma unroll
    for (int m = 0; m < M; m++) {
        int nb = __ldg(&idx[k * M + m]);
        float4 q = __ldg(&d_pk[nb]);
        float dx = q.x - pk.x;
        float dy = q.y - pk.y;
        float du = q.z - pk.z;
        float du1 = q.w - pk.w;
        sx  += du  * dx;  sy  += du  * dy;
        s1x += du1 * dx;  s1y += du1 * dy;
    }
    float4 iv = __ldg(&inv[k]);  // a=iv.x [0][0], b=iv.y [0][1], c=iv.z [1][0], d=iv.w [1][1]
    float4 g;
    g.x = sx * iv.x + sy * iv.z;   // out[0] = s_j0*inv[0][0] + s_j1... = sum_j u_ds[j]*inv[j][0]
    g.y = sx * iv.y + sy * iv.w;   // out[1] = sum_j u_ds[j]*inv[j][1]
    g.z = s1x * iv.x + s1y * iv.z;
    g.w = s1x * iv.y + s1y * iv.w;
    d_g[k] = g;
}

// K3: grad2 for both + f + loss_f
__global__ void k_grad2(const int* __restrict__ idx,
                        const float4* __restrict__ inv,
                        int n) {
    int k = blockIdx.x * blockDim.x + threadIdx.x;
    float ff = 0.0f;
    if (k < n) {
        float4 pk = d_pk[k];
        float4 gk = d_g[k];
        float s00 = 0.f, s01 = 0.f, s10 = 0.f, s11 = 0.f;
        float t00 = 0.f, t01 = 0.f, t10 = 0.f, t11 = 0.f;
        #pragma unroll
        for (int m = 0; m < M; m++) {
            int nb = __ldg(&idx[k * M + m]);
            float4 q  = __ldg(&d_pk[nb]);
            float4 gq = __ldg(&d_g[nb]);
            float dx = q.x - pk.x;
            float dy = q.y - pk.y;
            float d0 = gq.x - gk.x;   // u_xd comp 0 (ut)
            float d1 = gq.y - gk.y;   // u_xd comp 1 (ut)
            float e0 = gq.z - gk.z;   // (ut1)
            float e1 = gq.w - gk.w;
            s00 += d0 * dx; s01 += d0 * dy;
            s10 += d1 * dx; s11 += d1 * dy;
            t00 += e0 * dx; t01 += e0 * dy;
            t10 += e1 * dx; t11 += e1 * dy;
        }
        float4 iv = __ldg(&inv[k]);
        // out[i][l] = sum_j s[i][j] * inv[j][l]
        float u_xx  = s00 * iv.x + s01 * iv.z;  // out[0][0]
        float u_yy  = s10 * iv.y + s11 * iv.w;  // out[1][1]
        float u_xx1 = t00 * iv.x + t01 * iv.z;
        float u_yy1 = t10 * iv.y + t11 * iv.w;
        float utk  = pk.z;
        float ut1k = pk.w;
        float f = ut1k - utk
                - 0.01f * ((0.01f * (u_xx + u_yy) + utk - utk * utk * utk)
                         + (0.01f * (u_xx1 + u_yy1) + ut1k - ut1k * ut1k * ut1k));
        ff = f * f;
    }
    block_reduce_add(ff, &d_acc[1]);
}

__global__ void k_final(float* out) {
    out[0] = (float)(d_acc[0] + 4.0 * d_acc[1]);
}

extern "C" void kernel_launch(void* const* d_in, const int* in_sizes, int n_in,
                              void* d_out, int out_size) {
    const float* up   = (const float*)d_in[0];
    const float* usol = (const float*)d_in[1];
    const float* ut   = (const float*)d_in[2];
    const float* x    = (const float*)d_in[3];
    const float* ut1  = (const float*)d_in[4];
    const int*   idx  = (const int*)d_in[5];
    const float4* inv = (const float4*)d_in[6];
    int n = in_sizes[0];

    const int T = 256;
    int B = (n + T - 1) / T;

    k_init<<<1, 1>>>();
    k_pack<<<B, T>>>(up, usol, ut, x, ut1, n);
    k_grad1<<<B, T>>>(idx, inv, n);
    k_grad2<<<B, T>>>(idx, inv, n);
    k_final<<<1, 1>>>((float*)d_out);
}

// round 2
// speedup vs baseline: 1.0427x; 1.0427x over previous
#include <cuda_runtime.h>
#include <cstdint>

#define MAXN 1000000
#define M 9

// Scratch (allocation-free rule: __device__ globals)
__device__ float4 d_pk[MAXN];   // {x, y, ut, ut1}
__device__ float4 d_g[MAXN];    // {gx, gy, g1x, g1y}  (grad1 for ut and ut1)
__device__ double d_acc[2];     // [0] = loss_u, [1] = loss_f

__global__ void k_init() {
    d_acc[0] = 0.0;
    d_acc[1] = 0.0;
}

// Block-level reduce a float, one double atomicAdd per block.
__device__ __forceinline__ void block_reduce_add(float v, double* target) {
    __shared__ float warp_sums[32];
    int lane = threadIdx.x & 31;
    int wid  = threadIdx.x >> 5;
    #pragma unroll
    for (int off = 16; off > 0; off >>= 1)
        v += __shfl_down_sync(0xFFFFFFFFu, v, off);
    if (lane == 0) warp_sums[wid] = v;
    __syncthreads();
    int nwarps = (blockDim.x + 31) >> 5;
    if (wid == 0) {
        float s = (lane < nwarps) ? warp_sums[lane] : 0.0f;
        #pragma unroll
        for (int off = 16; off > 0; off >>= 1)
            s += __shfl_down_sync(0xFFFFFFFFu, s, off);
        if (lane == 0) atomicAdd(target, (double)s);
    }
}

// K1: build pack array + loss_u
__global__ void k_pack(const float* __restrict__ up,
                       const float* __restrict__ usol,
                       const float* __restrict__ ut,
                       const float* __restrict__ x,
                       const float* __restrict__ ut1,
                       int n) {
    int i = blockIdx.x * blockDim.x + threadIdx.x;
    float lu = 0.0f;
    if (i < n) {
        float4 pk;
        pk.x = x[2 * i];
        pk.y = x[2 * i + 1];
        pk.z = ut[i];
        pk.w = ut1[i];
        d_pk[i] = pk;
        float d = up[i] - usol[i];
        lu = d * d;
    }
    block_reduce_add(lu, &d_acc[0]);
}

// K2: grad1 for ut and ut1 simultaneously (shared x gathers via pack)
__global__ void k_grad1(const int* __restrict__ idx,
                        const float4* __restrict__ inv,
                        int n) {
    int k = blockIdx.x * blockDim.x + threadIdx.x;
    if (k >= n) return;
    float4 pk = d_pk[k];
    float sx = 0.f, sy = 0.f, s1x = 0.f, s1y = 0.f;
    #pragma unroll
    for (int m = 0; m < M; m++) {
        int nb = __ldg(&idx[k * M + m]);
        float4 q = __ldg(&d_pk[nb]);
        float dx = q.x - pk.x;
        float dy = q.y - pk.y;
        float du = q.z - pk.z;
        float du1 = q.w - pk.w;
        sx  += du  * dx;  sy  += du  * dy;
        s1x += du1 * dx;  s1y += du1 * dy;
    }
    float4 iv = __ldg(&inv[k]);  // a=iv.x [0][0], b=iv.y [0][1], c=iv.z [1][0], d=iv.w [1][1]
    float4 g;
    g.x = sx * iv.x + sy * iv.z;   // out[0] = s_j0*inv[0][0] + s_j1... = sum_j u_ds[j]*inv[j][0]
    g.y = sx * iv.y + sy * iv.w;   // out[1] = sum_j u_ds[j]*inv[j][1]
    g.z = s1x * iv.x + s1y * iv.z;
    g.w = s1x * iv.y + s1y * iv.w;
    d_g[k] = g;
}

// K3: grad2 for both + f + loss_f
__global__ void k_grad2(const int* __restrict__ idx,
                        const float4* __restrict__ inv,
                        int n) {
    int k = blockIdx.x * blockDim.x + threadIdx.x;
    float ff = 0.0f;
    if (k < n) {
        float4 pk = d_pk[k];
        float4 gk = d_g[k];
        float s00 = 0.f, s01 = 0.f, s10 = 0.f, s11 = 0.f;
        float t00 = 0.f, t01 = 0.f, t10 = 0.f, t11 = 0.f;
        #pragma unroll
        for (int m = 0; m < M; m++) {
            int nb = __ldg(&idx[k * M + m]);
            float4 q  = __ldg(&d_pk[nb]);
            float4 gq = __ldg(&d_g[nb]);
            float dx = q.x - pk.x;
            float dy = q.y - pk.y;
            float d0 = gq.x - gk.x;   // u_xd comp 0 (ut)
            float d1 = gq.y - gk.y;   // u_xd comp 1 (ut)
            float e0 = gq.z - gk.z;   // (ut1)
            float e1 = gq.w - gk.w;
            s00 += d0 * dx; s01 += d0 * dy;
            s10 += d1 * dx; s11 += d1 * dy;
            t00 += e0 * dx; t01 += e0 * dy;
            t10 += e1 * dx; t11 += e1 * dy;
        }
        float4 iv = __ldg(&inv[k]);
        // out[i][l] = sum_j s[i][j] * inv[j][l]
        float u_xx  = s00 * iv.x + s01 * iv.z;  // out[0][0]
        float u_yy  = s10 * iv.y + s11 * iv.w;  // out[1][1]
        float u_xx1 = t00 * iv.x + t01 * iv.z;
        float u_yy1 = t10 * iv.y + t11 * iv.w;
        float utk  = pk.z;
        float ut1k = pk.w;
        float f = ut1k - utk
                - 0.01f * ((0.01f * (u_xx + u_yy) + utk - utk * utk * utk)
                         + (0.01f * (u_xx1 + u_yy1) + ut1k - ut1k * ut1k * ut1k));
        ff = f * f;
    }
    block_reduce_add(ff, &d_acc[1]);
}

__global__ void k_final(float* out) {
    out[0] = (float)(d_acc[0] + 4.0 * d_acc[1]);
}

extern "C" void kernel_launch(void* const* d_in, const int* in_sizes, int n_in,
                              void* d_out, int out_size) {
    const float* up   = (const float*)d_in[0];
    const float* usol = (const float*)d_in[1];
    const float* ut   = (const float*)d_in[2];
    const float* x    = (const float*)d_in[3];
    const float* ut1  = (const float*)d_in[4];
    const int*   idx  = (const int*)d_in[5];
    const float4* inv = (const float4*)d_in[6];
    int n = in_sizes[0];

    const int T = 256;
    int B = (n + T - 1) / T;

    k_init<<<1, 1>>>();
    k_pack<<<B, T>>>(up, usol, ut, x, ut1, n);
    k_grad1<<<B, T>>>(idx, inv, n);
    k_grad2<<<B, T>>>(idx, inv, n);
    k_final<<<1, 1>>>((float*)d_out);
}

// round 3
// speedup vs baseline: 1.0559x; 1.0126x over previous
#include <cuda_runtime.h>
#include <cstdint>

#define MAXN 1000000
#define M 9

// Scratch (allocation-free rule: __device__ globals)
__device__ float4 d_pk[MAXN];   // {x, y, ut, ut1}
__device__ float4 d_g[MAXN];    // {gx, gy, g1x, g1y}  (grad1 for ut and ut1)
__device__ double d_acc[2];     // [0] = loss_u, [1] = loss_f

__global__ void k_init() {
    d_acc[0] = 0.0;
    d_acc[1] = 0.0;
}

// Block-level reduce a float, one double atomicAdd per block.
__device__ __forceinline__ void block_reduce_add(float v, double* target) {
    __shared__ float warp_sums[32];
    int lane = threadIdx.x & 31;
    int wid  = threadIdx.x >> 5;
    #pragma unroll
    for (int off = 16; off > 0; off >>= 1)
        v += __shfl_down_sync(0xFFFFFFFFu, v, off);
    if (lane == 0) warp_sums[wid] = v;
    __syncthreads();
    int nwarps = (blockDim.x + 31) >> 5;
    if (wid == 0) {
        float s = (lane < nwarps) ? warp_sums[lane] : 0.0f;
        #pragma unroll
        for (int off = 16; off > 0; off >>= 1)
            s += __shfl_down_sync(0xFFFFFFFFu, s, off);
        if (lane == 0) atomicAdd(target, (double)s);
    }
}

// K1: build pack array + loss_u
__global__ void k_pack(const float* __restrict__ up,
                       const float* __restrict__ usol,
                       const float* __restrict__ ut,
                       const float* __restrict__ x,
                       const float* __restrict__ ut1,
                       int n) {
    int i = blockIdx.x * blockDim.x + threadIdx.x;
    float lu = 0.0f;
    if (i < n) {
        float4 pk;
        pk.x = x[2 * i];
        pk.y = x[2 * i + 1];
        pk.z = ut[i];
        pk.w = ut1[i];
        d_pk[i] = pk;
        float d = up[i] - usol[i];
        lu = d * d;
    }
    block_reduce_add(lu, &d_acc[0]);
}

// K2: grad1 for ut and ut1 simultaneously (shared x gathers via pack)
__global__ void k_grad1(const int* __restrict__ idx,
                        const float4* __restrict__ inv,
                        int n) {
    int k = blockIdx.x * blockDim.x + threadIdx.x;
    if (k >= n) return;
    float4 pk = d_pk[k];
    float sx = 0.f, sy = 0.f, s1x = 0.f, s1y = 0.f;
    #pragma unroll
    for (int m = 0; m < M; m++) {
        int nb = __ldg(&idx[k * M + m]);
        float4 q = __ldg(&d_pk[nb]);
        float dx = q.x - pk.x;
        float dy = q.y - pk.y;
        float du = q.z - pk.z;
        float du1 = q.w - pk.w;
        sx  += du  * dx;  sy  += du  * dy;
        s1x += du1 * dx;  s1y += du1 * dy;
    }
    float4 iv = __ldg(&inv[k]);  // a=iv.x [0][0], b=iv.y [0][1], c=iv.z [1][0], d=iv.w [1][1]
    float4 g;
    g.x = sx * iv.x + sy * iv.z;   // out[0] = s_j0*inv[0][0] + s_j1... = sum_j u_ds[j]*inv[j][0]
    g.y = sx * iv.y + sy * iv.w;   // out[1] = sum_j u_ds[j]*inv[j][1]
    g.z = s1x * iv.x + s1y * iv.z;
    g.w = s1x * iv.y + s1y * iv.w;
    d_g[k] = g;
}

// K3: grad2 for both + f + loss_f
__global__ void k_grad2(const int* __restrict__ idx,
                        const float4* __restrict__ inv,
                        int n) {
    int k = blockIdx.x * blockDim.x + threadIdx.x;
    float ff = 0.0f;
    if (k < n) {
        float4 pk = d_pk[k];
        float4 gk = d_g[k];
        float s00 = 0.f, s01 = 0.f, s10 = 0.f, s11 = 0.f;
        float t00 = 0.f, t01 = 0.f, t10 = 0.f, t11 = 0.f;
        #pragma unroll
        for (int m = 0; m < M; m++) {
            int nb = __ldg(&idx[k * M + m]);
            float4 q  = __ldg(&d_pk[nb]);
            float4 gq = __ldg(&d_g[nb]);
            float dx = q.x - pk.x;
            float dy = q.y - pk.y;
            float d0 = gq.x - gk.x;   // u_xd comp 0 (ut)
            float d1 = gq.y - gk.y;   // u_xd comp 1 (ut)
            float e0 = gq.z - gk.z;   // (ut1)
            float e1 = gq.w - gk.w;
            s00 += d0 * dx; s01 += d0 * dy;
            s10 += d1 * dx; s11 += d1 * dy;
            t00 += e0 * dx; t01 += e0 * dy;
            t10 += e1 * dx; t11 += e1 * dy;
        }
        float4 iv = __ldg(&inv[k]);
        // out[i][l] = sum_j s[i][j] * inv[j][l]
        float u_xx  = s00 * iv.x + s01 * iv.z;  // out[0][0]
        float u_yy  = s10 * iv.y + s11 * iv.w;  // out[1][1]
        float u_xx1 = t00 * iv.x + t01 * iv.z;
        float u_yy1 = t10 * iv.y + t11 * iv.w;
        float utk  = pk.z;
        float ut1k = pk.w;
        float f = ut1k - utk
                - 0.01f * ((0.01f * (u_xx + u_yy) + utk - utk * utk * utk)
                         + (0.01f * (u_xx1 + u_yy1) + ut1k - ut1k * ut1k * ut1k));
        ff = f * f;
    }
    block_reduce_add(ff, &d_acc[1]);
}

__global__ void k_final(float* out) {
    out[0] = (float)(d_acc[0] + 4.0 * d_acc[1]);
}

extern "C" void kernel_launch(void* const* d_in, const int* in_sizes, int n_in,
                              void* d_out, int out_size) {
    const float* up   = (const float*)d_in[0];
    const float* usol = (const float*)d_in[1];
    const float* ut   = (const float*)d_in[2];
    const float* x    = (const float*)d_in[3];
    const float* ut1  = (const float*)d_in[4];
    const int*   idx  = (const int*)d_in[5];
    const float4* inv = (const float4*)d_in[6];
    int n = in_sizes[0];

    const int T = 256;
    int B = (n + T - 1) / T;

    k_init<<<1, 1>>>();
    k_pack<<<B, T>>>(up, usol, ut, x, ut1, n);
    k_grad1<<<B, T>>>(idx, inv, n);
    k_grad2<<<B, T>>>(idx, inv, n);
    k_final<<<1, 1>>>((float*)d_out);
}

// round 4
// speedup vs baseline: 1.3352x; 1.2645x over previous
#include <cuda_runtime.h>
#include <cuda_fp16.h>
#include <cstdint>

#define MAXN 1000000
#define M 9
#define T 256
#define IDX_PER_BLOCK (T * M)   // 2304 ints = 9216 bytes, 16B-aligned per block

// Scratch (allocation-free rule: __device__ globals)
__device__ float4 d_pk[MAXN];   // {x, y, ut, ut1} fp32 — grad1 gather
__device__ float4 d_gc[MAXN];   // {x, y, half2(g0,g1), half2(g2,g3)} — grad2 single gather
__device__ double d_acc[2];     // [0] = loss_u, [1] = loss_f

__global__ void k_init() {
    d_acc[0] = 0.0;
    d_acc[1] = 0.0;
}

__device__ __forceinline__ float pack_h2(float a, float b) {
    __half2 h = __floats2half2_rn(a, b);
    return *reinterpret_cast<float*>(&h);
}
__device__ __forceinline__ float2 unpack_h2(float bits) {
    __half2 h = *reinterpret_cast<__half2*>(&bits);
    return __half22float2(h);
}

// Block-level reduce a float, one double atomicAdd per block.
__device__ __forceinline__ void block_reduce_add(float v, double* target) {
    __shared__ float warp_sums[32];
    int lane = threadIdx.x & 31;
    int wid  = threadIdx.x >> 5;
    #pragma unroll
    for (int off = 16; off > 0; off >>= 1)
        v += __shfl_down_sync(0xFFFFFFFFu, v, off);
    if (lane == 0) warp_sums[wid] = v;
    __syncthreads();
    int nwarps = (blockDim.x + 31) >> 5;
    if (wid == 0) {
        float s = (lane < nwarps) ? warp_sums[lane] : 0.0f;
        #pragma unroll
        for (int off = 16; off > 0; off >>= 1)
            s += __shfl_down_sync(0xFFFFFFFFu, s, off);
        if (lane == 0) atomicAdd(target, (double)s);
    }
}

// Cooperative idx staging: coalesced uint4 loads -> smem, stride-9 LDS later
// (bank-conflict-free: gcd(9,32)==1).
__device__ __forceinline__ void stage_idx(const int* __restrict__ idx,
                                          int* s_idx, int n) {
    int blockBase = blockIdx.x * IDX_PER_BLOCK;      // element offset, mult of 2304
    int nint = n * M;                                 // 9e6 fits in int
    for (int t = threadIdx.x; t * 4 < IDX_PER_BLOCK; t += T) {
        int gi = blockBase + t * 4;
        if (gi + 3 < nint) {
            uint4 v = ((const uint4*)idx)[(blockBase >> 2) + t];
            *reinterpret_cast<uint4*>(&s_idx[t * 4]) = v;
        } else {
            #pragma unroll
            for (int j = 0; j < 4; j++)
                if (gi + j < nint) s_idx[t * 4 + j] = idx[gi + j];
        }
    }
    __syncthreads();
}

// K1: build pack array + loss_u
__global__ void k_pack(const float* __restrict__ up,
                       const float* __restrict__ usol,
                       const float* __restrict__ ut,
                       const float* __restrict__ x,
                       const float* __restrict__ ut1,
                       int n) {
    int i = blockIdx.x * blockDim.x + threadIdx.x;
    float lu = 0.0f;
    if (i < n) {
        float4 pk;
        pk.x = x[2 * i];
        pk.y = x[2 * i + 1];
        pk.z = ut[i];
        pk.w = ut1[i];
        d_pk[i] = pk;
        float d = up[i] - usol[i];
        lu = d * d;
    }
    block_reduce_add(lu, &d_acc[0]);
}

// K2: grad1 for ut and ut1 simultaneously; writes the combined
// {x, y, g(half)} struct consumed by grad2 as a single 16B gather.
__global__ void k_grad1(const int* __restrict__ idx,
                        const float4* __restrict__ inv,
                        int n) {
    __shared__ int s_idx[IDX_PER_BLOCK];
    stage_idx(idx, s_idx, n);

    int k = blockIdx.x * T + threadIdx.x;
    if (k >= n) return;

    int nb[M];
    #pragma unroll
    for (int m = 0; m < M; m++) nb[m] = s_idx[threadIdx.x * M + m];

    float4 pk = d_pk[k];
    float sx = 0.f, sy = 0.f, s1x = 0.f, s1y = 0.f;
    #pragma unroll
    for (int m = 0; m < M; m++) {
        float4 q = __ldg(&d_pk[nb[m]]);
        float dx = q.x - pk.x;
        float dy = q.y - pk.y;
        float du = q.z - pk.z;
        float du1 = q.w - pk.w;
        sx  += du  * dx;  sy  += du  * dy;
        s1x += du1 * dx;  s1y += du1 * dy;
    }
    float4 iv = __ldg(&inv[k]);
    float g0 = sx * iv.x + sy * iv.z;
    float g1 = sx * iv.y + sy * iv.w;
    float g2 = s1x * iv.x + s1y * iv.z;
    float g3 = s1x * iv.y + s1y * iv.w;

    float4 out;
    out.x = pk.x;
    out.y = pk.y;
    out.z = pack_h2(g0, g1);
    out.w = pack_h2(g2, g3);
    d_gc[k] = out;
}

// K3: grad2 for both + f + loss_f. ONE 16B gather per neighbor.
__global__ void k_grad2(const int* __restrict__ idx,
                        const float4* __restrict__ inv,
                        const float* __restrict__ ut,
                        const float* __restrict__ ut1,
                        int n) {
    __shared__ int s_idx[IDX_PER_BLOCK];
    stage_idx(idx, s_idx, n);

    int k = blockIdx.x * T + threadIdx.x;
    float ff = 0.0f;
    if (k < n) {
        int nb[M];
        #pragma unroll
        for (int m = 0; m < M; m++) nb[m] = s_idx[threadIdx.x * M + m];

        float4 gc = d_gc[k];
        float kx = gc.x, ky = gc.y;
        float2 gkA = unpack_h2(gc.z);   // g0, g1 (ut)
        float2 gkB = unpack_h2(gc.w);   // g2, g3 (ut1)

        float s00 = 0.f, s01 = 0.f, s10 = 0.f, s11 = 0.f;
        float t00 = 0.f, t01 = 0.f, t10 = 0.f, t11 = 0.f;
        #pragma unroll
        for (int m = 0; m < M; m++) {
            float4 q = __ldg(&d_gc[nb[m]]);
            float dx = q.x - kx;
            float dy = q.y - ky;
            float2 gA = unpack_h2(q.z);
            float2 gB = unpack_h2(q.w);
            float d0 = gA.x - gkA.x;
            float d1 = gA.y - gkA.y;
            float e0 = gB.x - gkB.x;
            float e1 = gB.y - gkB.y;
            s00 += d0 * dx; s01 += d0 * dy;
            s10 += d1 * dx; s11 += d1 * dy;
            t00 += e0 * dx; t01 += e0 * dy;
            t10 += e1 * dx; t11 += e1 * dy;
        }
        float4 iv = __ldg(&inv[k]);
        float u_xx  = s00 * iv.x + s01 * iv.z;  // out[0][0]
        float u_yy  = s10 * iv.y + s11 * iv.w;  // out[1][1]
        float u_xx1 = t00 * iv.x + t01 * iv.z;
        float u_yy1 = t10 * iv.y + t11 * iv.w;

        float utk  = ut[k];    // exact fp32 direct terms
        float ut1k = ut1[k];
        float f = ut1k - utk
                - 0.01f * ((0.01f * (u_xx + u_yy) + utk - utk * utk * utk)
                         + (0.01f * (u_xx1 + u_yy1) + ut1k - ut1k * ut1k * ut1k));
        ff = f * f;
    }
    block_reduce_add(ff, &d_acc[1]);
}

__global__ void k_final(float* out) {
    out[0] = (float)(d_acc[0] + 4.0 * d_acc[1]);
}

extern "C" void kernel_launch(void* const* d_in, const int* in_sizes, int n_in,
                              void* d_out, int out_size) {
    const float* up   = (const float*)d_in[0];
    const float* usol = (const float*)d_in[1];
    const float* ut   = (const float*)d_in[2];
    const float* x    = (const float*)d_in[3];
    const float* ut1  = (const float*)d_in[4];
    const int*   idx  = (const int*)d_in[5];
    const float4* inv = (const float4*)d_in[6];
    int n = in_sizes[0];

    int B = (n + T - 1) / T;

    k_init<<<1, 1>>>();
    k_pack<<<B, T>>>(up, usol, ut, x, ut1, n);
    k_grad1<<<B, T>>>(idx, inv, n);
    k_grad2<<<B, T>>>(idx, inv, ut, ut1, n);
    k_final<<<1, 1>>>((float*)d_out);
}